// round 2
// baseline (speedup 1.0000x reference)
#include <cuda_runtime.h>
#include <math.h>
#include <stdint.h>

// ---------------- problem constants ----------------
#define BB   64
#define IMGS 64
#define PPS  4
#define DD   1024
#define NN   257
#define HH   8
#define HD   128
#define DFF  4096
#define LLAY 8
#define MM   (BB * NN)          // 16448 rows in the token matrix

// ---------------- scratch (single device global, allocation-free) ----------
// layout (floats):
//   t    : [B*N*D]              @ 0
//   xn   : [B*N*D]              @ 1*S1
//   q    : [B*N*D]              @ 2*S1
//   k    : [B*N*D]              @ 3*S1
//   v    : [B*N*D]              @ 4*S1
//   y    : [B*N*D]              @ 5*S1
//   attn : [B*H*N*N]            @ 6*S1
//   h    : [M*DF]               @ 6*S1 + A2
#define S1   (BB * NN * DD)                  // 16,842,752
#define A2   (BB * HH * NN * NN)             // 33,817,088
#define HSZ  (MM * DFF)                      // 67,371,008
#define TOTAL_SCRATCH (6 * S1 + A2 + HSZ)    // 202,244,608 floats (~809 MB)

__device__ float g_scratch[TOTAL_SCRATCH];

// ---------------- patch embedding + pos emb ----------------
// t[b, 1+p, :] = conv(x)[b, p] + conv_b + pos_emb[1+p]
__global__ void patch_embed_kernel(const float* __restrict__ x,
                                   const float* __restrict__ w,
                                   const float* __restrict__ cbias,
                                   const float* __restrict__ pos,
                                   float* __restrict__ t)
{
    int bp = blockIdx.x;            // b*256 + p
    int b  = bp >> 8;
    int p  = bp & 255;
    int py = p >> 4, px = p & 15;

    __shared__ float patch[48];     // [kh][kw][c] = kh*12 + kw*3 + c
    int tid = threadIdx.x;
    if (tid < 48) {
        int c  = tid % 3;
        int kw = (tid / 3) & 3;
        int kh = tid / 12;
        patch[tid] = x[(((size_t)(b * IMGS + py * 4 + kh) * IMGS) + px * 4 + kw) * 3 + c];
    }
    __syncthreads();

    float* trow = t + (size_t)(b * NN + 1 + p) * DD;
    const float* posrow = pos + (size_t)(1 + p) * DD;
    for (int d = tid; d < DD; d += 256) {
        float acc = cbias[d];
#pragma unroll
        for (int i = 0; i < 48; i++)
            acc += patch[i] * w[i * DD + d];
        trow[d] = acc + posrow[d];
    }
}

// t[b, 0, :] = cls + pos_emb[0]
__global__ void cls_kernel(const float* __restrict__ cls,
                           const float* __restrict__ pos,
                           float* __restrict__ t)
{
    int b = blockIdx.x;
    for (int d = threadIdx.x; d < DD; d += 256)
        t[(size_t)b * NN * DD + d] = cls[d] + pos[d];
}

// ---------------- layernorm (one block per row, D=1024) ----------------
__global__ void ln_kernel(const float* __restrict__ in, float* __restrict__ out,
                          const float* __restrict__ g, const float* __restrict__ bta)
{
    int row = blockIdx.x;
    int tid = threadIdx.x;
    const float4* xr = (const float4*)(in + (size_t)row * DD);
    float4 xv = xr[tid];

    float s  = xv.x + xv.y + xv.z + xv.w;
    float ss = xv.x * xv.x + xv.y * xv.y + xv.z * xv.z + xv.w * xv.w;

#pragma unroll
    for (int o = 16; o; o >>= 1) {
        s  += __shfl_xor_sync(0xffffffffu, s, o);
        ss += __shfl_xor_sync(0xffffffffu, ss, o);
    }
    __shared__ float red[18];
    int w = tid >> 5, l = tid & 31;
    if (l == 0) { red[w] = s; red[8 + w] = ss; }
    __syncthreads();
    if (tid == 0) {
        float ts = 0.f, tss = 0.f;
#pragma unroll
        for (int i = 0; i < 8; i++) { ts += red[i]; tss += red[8 + i]; }
        float mean = ts * (1.f / DD);
        float var  = tss * (1.f / DD) - mean * mean;
        red[16] = mean;
        red[17] = rsqrtf(var + 1e-6f);
    }
    __syncthreads();
    float mean = red[16], rstd = red[17];

    float4 gv = ((const float4*)g)[tid];
    float4 bv = ((const float4*)bta)[tid];
    float4 ov;
    ov.x = (xv.x - mean) * rstd * gv.x + bv.x;
    ov.y = (xv.y - mean) * rstd * gv.y + bv.y;
    ov.z = (xv.z - mean) * rstd * gv.z + bv.z;
    ov.w = (xv.w - mean) * rstd * gv.w + bv.w;
    ((float4*)(out + (size_t)row * DD))[tid] = ov;
}

// ---------------- generic tiled SGEMM with batch + epilogue ----------------
// C = alpha * (A x op(B)) [+ bias] [gelu] [+ Res];  op(B) = B or B^T
// batch index z -> (zo = z / binner, zi = z % binner); per-operand 2-level strides.
#define BM 64
#define BN 64
#define BK 16

__global__ __launch_bounds__(256) void gemm_kernel(
    const float* __restrict__ A, const float* __restrict__ B, float* __restrict__ C,
    int M, int Nc, int K, int lda, int ldb, int ldc,
    int binner,
    long long sAo, long long sAi, long long sBo, long long sBi,
    long long sCo, long long sCi,
    const float* __restrict__ bias,
    const float* __restrict__ Res,
    float alpha, int transB, int doGelu)
{
    int z  = blockIdx.z;
    int zo = z / binner, zi = z - zo * binner;
    A += zo * sAo + zi * sAi;
    B += zo * sBo + zi * sBi;
    C += zo * sCo + zi * sCi;
    if (Res) Res += zo * sCo + zi * sCi;

    __shared__ float As[BK][BM];
    __shared__ float Bs[BK][BN];

    int tid = threadIdx.x;
    int tx = tid & 15, ty = tid >> 4;
    int m0 = blockIdx.y * BM;
    int n0 = blockIdx.x * BN;

    float acc[4][4] = {};

    int arow = tid >> 2;           // 0..63
    int acol = (tid & 3) * 4;      // 0,4,8,12
    int brow = tid >> 4;           // 0..15
    int bcol = (tid & 15) * 4;     // 0..60

    for (int k0 = 0; k0 < K; k0 += BK) {
        {   // A tile: [BM x BK] -> As[k][m]
            int mA = m0 + arow;
            bool mok = (mA < M);
            const float* ap = A + (size_t)mA * lda + k0 + acol;
#pragma unroll
            for (int j = 0; j < 4; j++) {
                int kk = k0 + acol + j;
                As[acol + j][arow] = (mok && kk < K) ? ap[j] : 0.f;
            }
        }
        if (!transB) {   // B tile: [BK x BN] -> Bs[k][n]
            int kB = k0 + brow;
            bool kok = (kB < K);
            const float* bp = B + (size_t)kB * ldb + n0 + bcol;
#pragma unroll
            for (int j = 0; j < 4; j++) {
                int nB = n0 + bcol + j;
                Bs[brow][bcol + j] = (kok && nB < Nc) ? bp[j] : 0.f;
            }
        } else {          // B is [Nc x K]; Bs[k][n] = B[n][k]
            int nB = n0 + arow;
            bool nok = (nB < Nc);
            const float* bp = B + (size_t)nB * ldb + k0 + acol;
#pragma unroll
            for (int j = 0; j < 4; j++) {
                int kk = k0 + acol + j;
                Bs[acol + j][arow] = (nok && kk < K) ? bp[j] : 0.f;
            }
        }
        __syncthreads();

#pragma unroll
        for (int kk = 0; kk < BK; kk++) {
            float a[4], bb[4];
#pragma unroll
            for (int i = 0; i < 4; i++) a[i] = As[kk][ty * 4 + i];
#pragma unroll
            for (int j = 0; j < 4; j++) bb[j] = Bs[kk][tx * 4 + j];
#pragma unroll
            for (int i = 0; i < 4; i++)
#pragma unroll
                for (int j = 0; j < 4; j++)
                    acc[i][j] += a[i] * bb[j];
        }
        __syncthreads();
    }

#pragma unroll
    for (int i = 0; i < 4; i++) {
        int m = m0 + ty * 4 + i;
        if (m >= M) continue;
#pragma unroll
        for (int j = 0; j < 4; j++) {
            int n = n0 + tx * 4 + j;
            if (n >= Nc) continue;
            float v = alpha * acc[i][j];
            if (bias) v += bias[n];
            if (doGelu) v = 0.5f * v * (1.0f + erff(v * 0.70710678118654752f));
            if (Res) v += Res[(size_t)m * ldc + n];
            C[(size_t)m * ldc + n] = v;
        }
    }
}

// ---------------- softmax over last dim (rows of length N=257) ----------
__global__ void softmax_kernel(float* __restrict__ S, int rows)
{
    int warp = (int)((blockIdx.x * (unsigned)blockDim.x + threadIdx.x) >> 5);
    int lane = threadIdx.x & 31;
    if (warp >= rows) return;
    float* row = S + (size_t)warp * NN;

    float vals[9];
    int cnt = 0;
    float mx = -1e30f;
    for (int c = lane; c < NN; c += 32) {
        float v = row[c];
        vals[cnt++] = v;
        mx = fmaxf(mx, v);
    }
#pragma unroll
    for (int o = 16; o; o >>= 1) mx = fmaxf(mx, __shfl_xor_sync(0xffffffffu, mx, o));
    float sum = 0.f;
    for (int i = 0; i < cnt; i++) { vals[i] = __expf(vals[i] - mx); sum += vals[i]; }
#pragma unroll
    for (int o = 16; o; o >>= 1) sum += __shfl_xor_sync(0xffffffffu, sum, o);
    float inv = 1.f / sum;
    cnt = 0;
    for (int c = lane; c < NN; c += 32) row[c] = vals[cnt++] * inv;
}

// ---------------- extract cls token ----------------
__global__ void extract_kernel(const float* __restrict__ t, float* __restrict__ out)
{
    int b = blockIdx.x;
    for (int d = threadIdx.x; d < DD; d += 256)
        out[(size_t)b * DD + d] = t[(size_t)b * NN * DD + d];
}

// ---------------- host driver ----------------
static inline void gemm(const float* A, const float* B, float* C,
                        int M, int Nc, int K, int lda, int ldb, int ldc,
                        int batch, int binner,
                        long long sAo, long long sAi, long long sBo, long long sBi,
                        long long sCo, long long sCi,
                        const float* bias, const float* Res,
                        float alpha, int transB, int doGelu)
{
    dim3 grid((Nc + BN - 1) / BN, (M + BM - 1) / BM, batch);
    gemm_kernel<<<grid, 256>>>(A, B, C, M, Nc, K, lda, ldb, ldc, binner,
                               sAo, sAi, sBo, sBi, sCo, sCi,
                               bias, Res, alpha, transB, doGelu);
}

extern "C" void kernel_launch(void* const* d_in, const int* in_sizes, int n_in,
                              void* d_out, int out_size)
{
    const float* x      = (const float*)d_in[0];
    const float* conv_w = (const float*)d_in[1];
    const float* conv_b = (const float*)d_in[2];
    const float* cls    = (const float*)d_in[3];
    const float* pos    = (const float*)d_in[4];
    const float* ln1_g  = (const float*)d_in[5];
    const float* ln1_b  = (const float*)d_in[6];
    const float* wq     = (const float*)d_in[7];
    const float* wk     = (const float*)d_in[8];
    const float* wv     = (const float*)d_in[9];
    const float* proj_w = (const float*)d_in[10];
    const float* proj_b = (const float*)d_in[11];
    const float* ln2_g  = (const float*)d_in[12];
    const float* ln2_b  = (const float*)d_in[13];
    const float* mlp1_w = (const float*)d_in[14];
    const float* mlp1_b = (const float*)d_in[15];
    const float* mlp2_w = (const float*)d_in[16];
    const float* mlp2_b = (const float*)d_in[17];
    float* out = (float*)d_out;

    float* scratch = nullptr;
    cudaGetSymbolAddress((void**)&scratch, g_scratch);
    float* t    = scratch;
    float* xn   = scratch + 1LL * S1;
    float* q    = scratch + 2LL * S1;
    float* k    = scratch + 3LL * S1;
    float* v    = scratch + 4LL * S1;
    float* y    = scratch + 5LL * S1;
    float* attn = scratch + 6LL * S1;
    float* hbuf = scratch + 6LL * S1 + A2;

    // --- patch embed + cls + pos ---
    patch_embed_kernel<<<BB * 256, 256>>>(x, conv_w, conv_b, pos, t);
    cls_kernel<<<BB, 256>>>(cls, pos, t);

    const float scale = 1.0f / sqrtf((float)HD);

    for (int i = 0; i < LLAY; i++) {
        // LN1
        ln_kernel<<<MM, 256>>>(t, xn, ln1_g + (size_t)i * DD, ln1_b + (size_t)i * DD);

        // QKV (scale folded into the score GEMM)
        gemm(xn, wq + (size_t)i * DD * DD, q, MM, DD, DD, DD, DD, DD,
             1, 1, 0, 0, 0, 0, 0, 0, nullptr, nullptr, 1.f, 0, 0);
        gemm(xn, wk + (size_t)i * DD * DD, k, MM, DD, DD, DD, DD, DD,
             1, 1, 0, 0, 0, 0, 0, 0, nullptr, nullptr, 1.f, 0, 0);
        gemm(xn, wv + (size_t)i * DD * DD, v, MM, DD, DD, DD, DD, DD,
             1, 1, 0, 0, 0, 0, 0, 0, nullptr, nullptr, 1.f, 0, 0);

        // scores: S[b,h] = scale * q[b,:,h,:] @ k[b,:,h,:]^T     (512 batches)
        gemm(q, k, attn, NN, NN, HD, DD, DD, NN,
             BB * HH, HH,
             (long long)NN * DD, HD,            // A strides (b, h)
             (long long)NN * DD, HD,            // B strides
             (long long)HH * NN * NN, (long long)NN * NN,  // C strides
             nullptr, nullptr, scale, 1, 0);

        // softmax over keys
        softmax_kernel<<<(BB * HH * NN + 7) / 8, 256>>>(attn, BB * HH * NN);

        // y[b,:,h,:] = S[b,h] @ v[b,:,h,:]
        gemm(attn, v, y, NN, HD, NN, NN, DD, DD,
             BB * HH, HH,
             (long long)HH * NN * NN, (long long)NN * NN,
             (long long)NN * DD, HD,
             (long long)NN * DD, HD,
             nullptr, nullptr, 1.f, 0, 0);

        // t = t + y @ proj_w + proj_b
        gemm(y, proj_w + (size_t)i * DD * DD, t, MM, DD, DD, DD, DD, DD,
             1, 1, 0, 0, 0, 0, 0, 0,
             proj_b + (size_t)i * DD, t, 1.f, 0, 0);

        // LN2
        ln_kernel<<<MM, 256>>>(t, xn, ln2_g + (size_t)i * DD, ln2_b + (size_t)i * DD);

        // h = gelu(xn @ mlp1_w + mlp1_b)
        gemm(xn, mlp1_w + (size_t)i * DD * DFF, hbuf, MM, DFF, DD, DD, DFF, DFF,
             1, 1, 0, 0, 0, 0, 0, 0,
             mlp1_b + (size_t)i * DFF, nullptr, 1.f, 0, 1);

        // t = t + h @ mlp2_w + mlp2_b
        gemm(hbuf, mlp2_w + (size_t)i * DFF * DD, t, MM, DD, DFF, DFF, DD, DD,
             1, 1, 0, 0, 0, 0, 0, 0,
             mlp2_b + (size_t)i * DD, t, 1.f, 0, 0);
    }

    extract_kernel<<<BB, 256>>>(t, out);
}

// round 5
// speedup vs baseline: 1.9962x; 1.9962x over previous
#include <cuda_runtime.h>
#include <cuda_bf16.h>
#include <math.h>
#include <stdint.h>

// ---------------- problem constants ----------------
#define BB   64
#define IMGS 64
#define DD   1024
#define NN   257
#define NPAD 272            // padded attn row stride (16B-aligned float4 rows)
#define HH   8
#define HD   128
#define DFF  4096
#define LLAY 8
#define MM   (BB * NN)      // 16448

// ---------------- scratch ----------------
#define S1   (BB * NN * DD)                       // 16,842,752
#define APAD (BB * HH * NN * NPAD)                // 35,790,848
#define HSZ  (MM * DFF)                           // 67,371,008
#define TOTAL_SCRATCH (6 * S1 + APAD + HSZ)
__device__ float g_scratch[TOTAL_SCRATCH];

// ---------------- patch embedding ----------------
__global__ void patch_embed_kernel(const float* __restrict__ x,
                                   const float* __restrict__ w,
                                   const float* __restrict__ cbias,
                                   const float* __restrict__ pos,
                                   float* __restrict__ t)
{
    int bp = blockIdx.x;
    int b  = bp >> 8;
    int p  = bp & 255;
    int py = p >> 4, px = p & 15;

    __shared__ float patch[48];
    int tid = threadIdx.x;
    if (tid < 48) {
        int c  = tid % 3;
        int kw = (tid / 3) & 3;
        int kh = tid / 12;
        patch[tid] = x[(((size_t)(b * IMGS + py * 4 + kh) * IMGS) + px * 4 + kw) * 3 + c];
    }
    __syncthreads();

    float* trow = t + (size_t)(b * NN + 1 + p) * DD;
    const float* posrow = pos + (size_t)(1 + p) * DD;
    for (int d = tid; d < DD; d += 256) {
        float acc = cbias[d];
#pragma unroll
        for (int i = 0; i < 48; i++)
            acc += patch[i] * w[i * DD + d];
        trow[d] = acc + posrow[d];
    }
}

__global__ void cls_kernel(const float* __restrict__ cls,
                           const float* __restrict__ pos,
                           float* __restrict__ t)
{
    int b = blockIdx.x;
    for (int d = threadIdx.x; d < DD; d += 256)
        t[(size_t)b * NN * DD + d] = cls[d] + pos[d];
}

// ---------------- layernorm ----------------
__global__ void ln_kernel(const float* __restrict__ in, float* __restrict__ out,
                          const float* __restrict__ g, const float* __restrict__ bta)
{
    int row = blockIdx.x;
    int tid = threadIdx.x;
    const float4* xr = (const float4*)(in + (size_t)row * DD);
    float4 xv = xr[tid];

    float s  = xv.x + xv.y + xv.z + xv.w;
    float ss = xv.x * xv.x + xv.y * xv.y + xv.z * xv.z + xv.w * xv.w;

#pragma unroll
    for (int o = 16; o; o >>= 1) {
        s  += __shfl_xor_sync(0xffffffffu, s, o);
        ss += __shfl_xor_sync(0xffffffffu, ss, o);
    }
    __shared__ float red[18];
    int w = tid >> 5, l = tid & 31;
    if (l == 0) { red[w] = s; red[8 + w] = ss; }
    __syncthreads();
    if (tid == 0) {
        float ts = 0.f, tss = 0.f;
#pragma unroll
        for (int i = 0; i < 8; i++) { ts += red[i]; tss += red[8 + i]; }
        float mean = ts * (1.f / DD);
        float var  = tss * (1.f / DD) - mean * mean;
        red[16] = mean;
        red[17] = rsqrtf(var + 1e-6f);
    }
    __syncthreads();
    float mean = red[16], rstd = red[17];

    float4 gv = ((const float4*)g)[tid];
    float4 bv = ((const float4*)bta)[tid];
    float4 ov;
    ov.x = (xv.x - mean) * rstd * gv.x + bv.x;
    ov.y = (xv.y - mean) * rstd * gv.y + bv.y;
    ov.z = (xv.z - mean) * rstd * gv.z + bv.z;
    ov.w = (xv.w - mean) * rstd * gv.w + bv.w;
    ((float4*)(out + (size_t)row * DD))[tid] = ov;
}

// ---------------- bf16x3 tensor-core GEMM ----------------
// C = alpha*(A x op(B)) [+bias][gelu][+Res], fp32 I/O, bf16 hi/lo split compute.
#define BM 128
#define BN 128
#define BK 32

__device__ __forceinline__ void bsplit2(float x, float y, uint32_t& hi, uint32_t& lo)
{
    __nv_bfloat16 hx = __float2bfloat16_rn(x);
    __nv_bfloat16 hy = __float2bfloat16_rn(y);
    __nv_bfloat16 lx = __float2bfloat16_rn(x - __bfloat162float(hx));
    __nv_bfloat16 ly = __float2bfloat16_rn(y - __bfloat162float(hy));
    hi = (uint32_t)__bfloat16_as_ushort(hx) | ((uint32_t)__bfloat16_as_ushort(hy) << 16);
    lo = (uint32_t)__bfloat16_as_ushort(lx) | ((uint32_t)__bfloat16_as_ushort(ly) << 16);
}

__device__ __forceinline__ void mma16816(float* c, const uint32_t* a, const uint32_t* b)
{
    asm volatile(
        "mma.sync.aligned.m16n8k16.row.col.f32.bf16.bf16.f32 "
        "{%0,%1,%2,%3},{%4,%5,%6,%7},{%8,%9},{%0,%1,%2,%3};\n"
        : "+f"(c[0]), "+f"(c[1]), "+f"(c[2]), "+f"(c[3])
        : "r"(a[0]), "r"(a[1]), "r"(a[2]), "r"(a[3]), "r"(b[0]), "r"(b[1]));
}

#define ASTR 40     // As row stride (bf16)
#define BSTR 136    // Bs row stride (bf16)

__global__ __launch_bounds__(256) void gemm_kernel(
    const float* __restrict__ A, const float* __restrict__ B, float* __restrict__ C,
    int M, int Nc, int K, int lda, int ldb, int ldc,
    int binner,
    long long sAo, long long sAi, long long sBo, long long sBi,
    long long sCo, long long sCi,
    const float* __restrict__ bias,
    const float* __restrict__ Res,
    float alpha, int transB, int doGelu)
{
    int z  = blockIdx.z;
    int zo = z / binner, zi = z - zo * binner;
    A += zo * sAo + zi * sAi;
    B += zo * sBo + zi * sBi;
    C += zo * sCo + zi * sCi;
    if (Res) Res += zo * sCo + zi * sCi;

    __shared__ __nv_bfloat16 AsH[BM][ASTR], AsL[BM][ASTR];
    __shared__ __nv_bfloat16 BsH[BK][BSTR], BsL[BK][BSTR];

    int tid  = threadIdx.x;
    int lane = tid & 31, wid = tid >> 5;
    int wm = wid >> 2, wn = wid & 3;      // warp tile: 64 x 32
    int g  = lane >> 2, t4 = lane & 3;
    int m0 = blockIdx.y * BM;
    int n0 = blockIdx.x * BN;

    float acc[4][4][4];
#pragma unroll
    for (int i = 0; i < 4; i++)
#pragma unroll
        for (int j = 0; j < 4; j++)
#pragma unroll
            for (int r = 0; r < 4; r++) acc[i][j][r] = 0.f;

    for (int k0 = 0; k0 < K; k0 += BK) {
        // ---- load A tile [BM x BK] ----
#pragma unroll
        for (int i = 0; i < 4; i++) {
            int slot = tid + i * 256;          // 1024 slots = 128 rows x 8 f4
            int mr = slot >> 3, c4 = slot & 7;
            int m = m0 + mr, kk = k0 + c4 * 4;
            float4 v = make_float4(0.f, 0.f, 0.f, 0.f);
            if (m < M) {
                const float* p = A + (size_t)m * lda + kk;
                if (kk + 3 < K) v = *(const float4*)p;
                else {
                    if (kk     < K) v.x = p[0];
                    if (kk + 1 < K) v.y = p[1];
                    if (kk + 2 < K) v.z = p[2];
                    if (kk + 3 < K) v.w = p[3];
                }
            }
            uint32_t h0, l0, h1, l1;
            bsplit2(v.x, v.y, h0, l0);
            bsplit2(v.z, v.w, h1, l1);
            *(uint32_t*)&AsH[mr][c4 * 4]     = h0;
            *(uint32_t*)&AsH[mr][c4 * 4 + 2] = h1;
            *(uint32_t*)&AsL[mr][c4 * 4]     = l0;
            *(uint32_t*)&AsL[mr][c4 * 4 + 2] = l1;
        }

        // ---- load B tile -> Bs[k][n] ----
        if (!transB) {
#pragma unroll
            for (int i = 0; i < 4; i++) {
                int slot = tid + i * 256;      // 32 rows x 32 f4
                int kr = slot >> 5, c4 = slot & 31;
                int kk = k0 + kr, nn = n0 + c4 * 4;
                float4 v = make_float4(0.f, 0.f, 0.f, 0.f);
                if (kk < K) {
                    const float* p = B + (size_t)kk * ldb + nn;
                    if (nn + 3 < Nc) v = *(const float4*)p;
                    else {
                        if (nn     < Nc) v.x = p[0];
                        if (nn + 1 < Nc) v.y = p[1];
                        if (nn + 2 < Nc) v.z = p[2];
                        if (nn + 3 < Nc) v.w = p[3];
                    }
                }
                uint32_t h0, l0, h1, l1;
                bsplit2(v.x, v.y, h0, l0);
                bsplit2(v.z, v.w, h1, l1);
                *(uint32_t*)&BsH[kr][c4 * 4]     = h0;
                *(uint32_t*)&BsH[kr][c4 * 4 + 2] = h1;
                *(uint32_t*)&BsL[kr][c4 * 4]     = l0;
                *(uint32_t*)&BsL[kr][c4 * 4 + 2] = l1;
            }
        } else {
            // gmem B is [Nc x K]; transpose into Bs[k][n]
#pragma unroll
            for (int i = 0; i < 4; i++) {
                int slot = tid + i * 256;      // 128 n-rows x 8 f4 along k
                int nr = slot >> 3, c4 = slot & 7;
                int nn = n0 + nr, kk = k0 + c4 * 4;
                float4 v = make_float4(0.f, 0.f, 0.f, 0.f);
                if (nn < Nc) {
                    const float* p = B + (size_t)nn * ldb + kk;
                    if (kk + 3 < K) v = *(const float4*)p;
                    else {
                        if (kk     < K) v.x = p[0];
                        if (kk + 1 < K) v.y = p[1];
                        if (kk + 2 < K) v.z = p[2];
                        if (kk + 3 < K) v.w = p[3];
                    }
                }
                int kl = c4 * 4;
                float vv[4] = {v.x, v.y, v.z, v.w};
#pragma unroll
                for (int j = 0; j < 4; j++) {
                    __nv_bfloat16 h = __float2bfloat16_rn(vv[j]);
                    __nv_bfloat16 l = __float2bfloat16_rn(vv[j] - __bfloat162float(h));
                    BsH[kl + j][nr] = h;
                    BsL[kl + j][nr] = l;
                }
            }
        }
        __syncthreads();

        // ---- MMA over 2 k16 steps ----
#pragma unroll
        for (int ks = 0; ks < 2; ks++) {
            int kb = ks * 16;
            uint32_t aH[4][4], aL[4][4], bH[4][2], bL[4][2];
#pragma unroll
            for (int mi = 0; mi < 4; mi++) {
                int r = wm * 64 + mi * 16 + g;
                aH[mi][0] = *(const uint32_t*)&AsH[r    ][kb + 2 * t4];
                aH[mi][1] = *(const uint32_t*)&AsH[r + 8][kb + 2 * t4];
                aH[mi][2] = *(const uint32_t*)&AsH[r    ][kb + 2 * t4 + 8];
                aH[mi][3] = *(const uint32_t*)&AsH[r + 8][kb + 2 * t4 + 8];
                aL[mi][0] = *(const uint32_t*)&AsL[r    ][kb + 2 * t4];
                aL[mi][1] = *(const uint32_t*)&AsL[r + 8][kb + 2 * t4];
                aL[mi][2] = *(const uint32_t*)&AsL[r    ][kb + 2 * t4 + 8];
                aL[mi][3] = *(const uint32_t*)&AsL[r + 8][kb + 2 * t4 + 8];
            }
#pragma unroll
            for (int ni = 0; ni < 4; ni++) {
                int c = wn * 32 + ni * 8 + g;
                int kr = kb + 2 * t4;
                bH[ni][0] = (uint32_t)__bfloat16_as_ushort(BsH[kr    ][c]) |
                            ((uint32_t)__bfloat16_as_ushort(BsH[kr + 1][c]) << 16);
                bH[ni][1] = (uint32_t)__bfloat16_as_ushort(BsH[kr + 8][c]) |
                            ((uint32_t)__bfloat16_as_ushort(BsH[kr + 9][c]) << 16);
                bL[ni][0] = (uint32_t)__bfloat16_as_ushort(BsL[kr    ][c]) |
                            ((uint32_t)__bfloat16_as_ushort(BsL[kr + 1][c]) << 16);
                bL[ni][1] = (uint32_t)__bfloat16_as_ushort(BsL[kr + 8][c]) |
                            ((uint32_t)__bfloat16_as_ushort(BsL[kr + 9][c]) << 16);
            }
#pragma unroll
            for (int mi = 0; mi < 4; mi++)
#pragma unroll
                for (int ni = 0; ni < 4; ni++) {
                    mma16816(acc[mi][ni], aH[mi], bH[ni]);
                    mma16816(acc[mi][ni], aH[mi], bL[ni]);
                    mma16816(acc[mi][ni], aL[mi], bH[ni]);
                }
        }
        __syncthreads();
    }

    // ---- epilogue ----
#pragma unroll
    for (int mi = 0; mi < 4; mi++) {
        int r0 = m0 + wm * 64 + mi * 16 + g;
#pragma unroll
        for (int ni = 0; ni < 4; ni++) {
            int c0 = n0 + wn * 32 + ni * 8 + 2 * t4;
#pragma unroll
            for (int rr = 0; rr < 2; rr++) {
                int r = r0 + rr * 8;
                if (r >= M) continue;
#pragma unroll
                for (int cc = 0; cc < 2; cc++) {
                    int c = c0 + cc;
                    if (c >= Nc) continue;
                    float v = alpha * acc[mi][ni][rr * 2 + cc];
                    if (bias) v += bias[c];
                    if (doGelu) v = 0.5f * v * (1.0f + erff(v * 0.70710678118654752f));
                    if (Res) v += Res[(size_t)r * ldc + c];
                    C[(size_t)r * ldc + c] = v;
                }
            }
        }
    }
}

// ---------------- softmax (rows of 257, stride NPAD) ----------------
__global__ void softmax_kernel(float* __restrict__ S, int rows)
{
    int warp = (int)((blockIdx.x * (unsigned)blockDim.x + threadIdx.x) >> 5);
    int lane = threadIdx.x & 31;
    if (warp >= rows) return;
    float* row = S + (size_t)warp * NPAD;

    float vals[9];
    int cnt = 0;
    float mx = -1e30f;
    for (int c = lane; c < NN; c += 32) {
        float v = row[c];
        vals[cnt++] = v;
        mx = fmaxf(mx, v);
    }
#pragma unroll
    for (int o = 16; o; o >>= 1) mx = fmaxf(mx, __shfl_xor_sync(0xffffffffu, mx, o));
    float sum = 0.f;
    for (int i = 0; i < cnt; i++) { vals[i] = __expf(vals[i] - mx); sum += vals[i]; }
#pragma unroll
    for (int o = 16; o; o >>= 1) sum += __shfl_xor_sync(0xffffffffu, sum, o);
    float inv = 1.f / sum;
    cnt = 0;
    for (int c = lane; c < NN; c += 32) row[c] = vals[cnt++] * inv;
}

__global__ void extract_kernel(const float* __restrict__ t, float* __restrict__ out)
{
    int b = blockIdx.x;
    for (int d = threadIdx.x; d < 256; d += 256) {}
    for (int d = threadIdx.x; d < DD; d += 256)
        out[(size_t)b * DD + d] = t[(size_t)b * NN * DD + d];
}

// ---------------- host driver ----------------
static inline void gemm(const float* A, const float* B, float* C,
                        int M, int Nc, int K, int lda, int ldb, int ldc,
                        int batch, int binner,
                        long long sAo, long long sAi, long long sBo, long long sBi,
                        long long sCo, long long sCi,
                        const float* bias, const float* Res,
                        float alpha, int transB, int doGelu)
{
    dim3 grid((Nc + BN - 1) / BN, (M + BM - 1) / BM, batch);
    gemm_kernel<<<grid, 256>>>(A, B, C, M, Nc, K, lda, ldb, ldc, binner,
                               sAo, sAi, sBo, sBi, sCo, sCi,
                               bias, Res, alpha, transB, doGelu);
}

extern "C" void kernel_launch(void* const* d_in, const int* in_sizes, int n_in,
                              void* d_out, int out_size)
{
    const float* x      = (const float*)d_in[0];
    const float* conv_w = (const float*)d_in[1];
    const float* conv_b = (const float*)d_in[2];
    const float* cls    = (const float*)d_in[3];
    const float* pos    = (const float*)d_in[4];
    const float* ln1_g  = (const float*)d_in[5];
    const float* ln1_b  = (const float*)d_in[6];
    const float* wq     = (const float*)d_in[7];
    const float* wk     = (const float*)d_in[8];
    const float* wv     = (const float*)d_in[9];
    const float* proj_w = (const float*)d_in[10];
    const float* proj_b = (const float*)d_in[11];
    const float* ln2_g  = (const float*)d_in[12];
    const float* ln2_b  = (const float*)d_in[13];
    const float* mlp1_w = (const float*)d_in[14];
    const float* mlp1_b = (const float*)d_in[15];
    const float* mlp2_w = (const float*)d_in[16];
    const float* mlp2_b = (const float*)d_in[17];
    float* out = (float*)d_out;

    float* scratch = nullptr;
    cudaGetSymbolAddress((void**)&scratch, g_scratch);
    float* t    = scratch;
    float* xn   = scratch + 1LL * S1;
    float* q    = scratch + 2LL * S1;
    float* k    = scratch + 3LL * S1;
    float* v    = scratch + 4LL * S1;
    float* y    = scratch + 5LL * S1;
    float* attn = scratch + 6LL * S1;
    float* hbuf = scratch + 6LL * S1 + APAD;

    patch_embed_kernel<<<BB * 256, 256>>>(x, conv_w, conv_b, pos, t);
    cls_kernel<<<BB, 256>>>(cls, pos, t);

    const float scale = 1.0f / sqrtf((float)HD);
    const long long aBlk = (long long)NN * NPAD;   // one (b,h) attn block

    for (int i = 0; i < LLAY; i++) {
        ln_kernel<<<MM, 256>>>(t, xn, ln1_g + (size_t)i * DD, ln1_b + (size_t)i * DD);

        gemm(xn, wq + (size_t)i * DD * DD, q, MM, DD, DD, DD, DD, DD,
             1, 1, 0, 0, 0, 0, 0, 0, nullptr, nullptr, 1.f, 0, 0);
        gemm(xn, wk + (size_t)i * DD * DD, k, MM, DD, DD, DD, DD, DD,
             1, 1, 0, 0, 0, 0, 0, 0, nullptr, nullptr, 1.f, 0, 0);
        gemm(xn, wv + (size_t)i * DD * DD, v, MM, DD, DD, DD, DD, DD,
             1, 1, 0, 0, 0, 0, 0, 0, nullptr, nullptr, 1.f, 0, 0);

        // scores: attn[b,h] = scale * q[b,:,h,:] @ k[b,:,h,:]^T
        gemm(q, k, attn, NN, NN, HD, DD, DD, NPAD,
             BB * HH, HH,
             (long long)NN * DD, HD,
             (long long)NN * DD, HD,
             (long long)HH * aBlk, aBlk,
             nullptr, nullptr, scale, 1, 0);

        softmax_kernel<<<(BB * HH * NN + 7) / 8, 256>>>(attn, BB * HH * NN);

        // y[b,:,h,:] = attn[b,h] @ v[b,:,h,:]
        gemm(attn, v, y, NN, HD, NN, NPAD, DD, DD,
             BB * HH, HH,
             (long long)HH * aBlk, aBlk,
             (long long)NN * DD, HD,
             (long long)NN * DD, HD,
             nullptr, nullptr, 1.f, 0, 0);

        gemm(y, proj_w + (size_t)i * DD * DD, t, MM, DD, DD, DD, DD, DD,
             1, 1, 0, 0, 0, 0, 0, 0,
             proj_b + (size_t)i * DD, t, 1.f, 0, 0);

        ln_kernel<<<MM, 256>>>(t, xn, ln2_g + (size_t)i * DD, ln2_b + (size_t)i * DD);

        gemm(xn, mlp1_w + (size_t)i * DD * DFF, hbuf, MM, DFF, DD, DD, DFF, DFF,
             1, 1, 0, 0, 0, 0, 0, 0,
             mlp1_b + (size_t)i * DFF, nullptr, 1.f, 0, 1);

        gemm(hbuf, mlp2_w + (size_t)i * DFF * DD, t, MM, DD, DFF, DFF, DD, DD,
             1, 1, 0, 0, 0, 0, 0, 0,
             mlp2_b + (size_t)i * DD, t, 1.f, 0, 0);
    }

    extract_kernel<<<BB, 256>>>(t, out);
}